// round 1
// baseline (speedup 1.0000x reference)
#include <cuda_runtime.h>
#include <math.h>

// LSTM cell: B=4096, I=H=1024.
// ifgo[4096,4096] = x@w_i + h@w_h + (b_i+b_h); gates -> h_new, c_new.
// Kernel 1: SIMT fp32 tiled GEMM over virtual K=2048 (x|h concat), writes ifgo scratch.
// Kernel 2: elementwise gate activations, writes d_out = [h_new (4M) | c_new (4M)].

#define BM 128
#define BN 128
#define BK 16

// 64 MB scratch for pre-activation gates (allocation-free rule: __device__ global).
__device__ float g_ifgo[4096ull * 4096ull];

__global__ __launch_bounds__(256, 2)
void lstm_gemm_kernel(const float* __restrict__ x,
                      const float* __restrict__ h,
                      const float* __restrict__ wi,
                      const float* __restrict__ wh,
                      const float* __restrict__ bi,
                      const float* __restrict__ bh)
{
    __shared__ float As[BK][BM];   // A transposed: As[k][m]
    __shared__ float Bs[BK][BN];   // Bs[k][n]

    const int bm  = blockIdx.y * BM;
    const int bn  = blockIdx.x * BN;
    const int tid = threadIdx.x;        // 256 threads
    const int tr  = tid >> 4;           // 0..15 (thread row group)
    const int tc  = tid & 15;           // 0..15 (thread col group)

    float acc[8][8];
    #pragma unroll
    for (int i = 0; i < 8; i++)
        #pragma unroll
        for (int j = 0; j < 8; j++) acc[i][j] = 0.f;

    // A-tile load mapping: 128 rows x 16 cols = 512 float4, 2 per thread
    const int a_row = tid >> 2;         // 0..63 (second load: +64)
    const int a_c4  = tid & 3;          // float4 column within BK
    // B-tile load mapping: 16 rows x 32 float4-cols = 512 float4, 2 per thread
    const int b_row = tid >> 5;         // 0..7 (second load: +8)
    const int b_c4  = tid & 31;

    for (int k0 = 0; k0 < 2048; k0 += BK) {
        const float* __restrict__ src = (k0 < 1024) ? x  : h;
        const float* __restrict__ w   = (k0 < 1024) ? wi : wh;
        const int kk = k0 & 1023;

        // ---- load A tile (transpose into As[k][m]) ----
        {
            float4 va = *reinterpret_cast<const float4*>(
                &src[(size_t)(bm + a_row) * 1024 + kk + a_c4 * 4]);
            As[a_c4 * 4 + 0][a_row] = va.x;
            As[a_c4 * 4 + 1][a_row] = va.y;
            As[a_c4 * 4 + 2][a_row] = va.z;
            As[a_c4 * 4 + 3][a_row] = va.w;
            float4 vb = *reinterpret_cast<const float4*>(
                &src[(size_t)(bm + a_row + 64) * 1024 + kk + a_c4 * 4]);
            As[a_c4 * 4 + 0][a_row + 64] = vb.x;
            As[a_c4 * 4 + 1][a_row + 64] = vb.y;
            As[a_c4 * 4 + 2][a_row + 64] = vb.z;
            As[a_c4 * 4 + 3][a_row + 64] = vb.w;
        }
        // ---- load B tile ----
        {
            *reinterpret_cast<float4*>(&Bs[b_row][b_c4 * 4]) =
                *reinterpret_cast<const float4*>(
                    &w[(size_t)(kk + b_row) * 4096 + bn + b_c4 * 4]);
            *reinterpret_cast<float4*>(&Bs[b_row + 8][b_c4 * 4]) =
                *reinterpret_cast<const float4*>(
                    &w[(size_t)(kk + b_row + 8) * 4096 + bn + b_c4 * 4]);
        }
        __syncthreads();

        // ---- compute 8x8 per thread ----
        #pragma unroll
        for (int k = 0; k < BK; k++) {
            float4 a0 = *reinterpret_cast<const float4*>(&As[k][tr * 8]);
            float4 a1 = *reinterpret_cast<const float4*>(&As[k][tr * 8 + 4]);
            float4 b0 = *reinterpret_cast<const float4*>(&Bs[k][tc * 8]);
            float4 b1 = *reinterpret_cast<const float4*>(&Bs[k][tc * 8 + 4]);
            float ra[8] = {a0.x, a0.y, a0.z, a0.w, a1.x, a1.y, a1.z, a1.w};
            float rb[8] = {b0.x, b0.y, b0.z, b0.w, b1.x, b1.y, b1.z, b1.w};
            #pragma unroll
            for (int i = 0; i < 8; i++)
                #pragma unroll
                for (int j = 0; j < 8; j++)
                    acc[i][j] = fmaf(ra[i], rb[j], acc[i][j]);
        }
        __syncthreads();
    }

    // ---- epilogue: add bias, store to scratch ----
    const int n0 = bn + tc * 8;
    float bsum[8];
    #pragma unroll
    for (int j = 0; j < 8; j++) bsum[j] = bi[n0 + j] + bh[n0 + j];

    #pragma unroll
    for (int i = 0; i < 8; i++) {
        const int m = bm + tr * 8 + i;
        float4 o0, o1;
        o0.x = acc[i][0] + bsum[0];
        o0.y = acc[i][1] + bsum[1];
        o0.z = acc[i][2] + bsum[2];
        o0.w = acc[i][3] + bsum[3];
        o1.x = acc[i][4] + bsum[4];
        o1.y = acc[i][5] + bsum[5];
        o1.z = acc[i][6] + bsum[6];
        o1.w = acc[i][7] + bsum[7];
        *reinterpret_cast<float4*>(&g_ifgo[(size_t)m * 4096 + n0])     = o0;
        *reinterpret_cast<float4*>(&g_ifgo[(size_t)m * 4096 + n0 + 4]) = o1;
    }
}

__device__ __forceinline__ float sigmoidf_fast(float v) {
    return 1.f / (1.f + __expf(-v));
}

__global__ __launch_bounds__(256)
void lstm_act_kernel(const float* __restrict__ c_t, float* __restrict__ out)
{
    // One float4 (4 hidden units) per thread. 4096*1024/4 = 1,048,576 float4.
    const int idx = blockIdx.x * blockDim.x + threadIdx.x;
    const int b  = idx >> 8;     // 256 float4 per hidden row
    const int hq = idx & 255;

    const float4* row = reinterpret_cast<const float4*>(g_ifgo + (size_t)b * 4096);
    float4 vi = row[hq];
    float4 vf = row[hq + 256];
    float4 vg = row[hq + 512];
    float4 vo = row[hq + 768];
    float4 vc = reinterpret_cast<const float4*>(c_t)[idx];

    float4 cn, hn;
    cn.x = sigmoidf_fast(vf.x) * vc.x + sigmoidf_fast(vi.x) * tanhf(vg.x);
    cn.y = sigmoidf_fast(vf.y) * vc.y + sigmoidf_fast(vi.y) * tanhf(vg.y);
    cn.z = sigmoidf_fast(vf.z) * vc.z + sigmoidf_fast(vi.z) * tanhf(vg.z);
    cn.w = sigmoidf_fast(vf.w) * vc.w + sigmoidf_fast(vi.w) * tanhf(vg.w);
    hn.x = sigmoidf_fast(vo.x) * tanhf(cn.x);
    hn.y = sigmoidf_fast(vo.y) * tanhf(cn.y);
    hn.z = sigmoidf_fast(vo.z) * tanhf(cn.z);
    hn.w = sigmoidf_fast(vo.w) * tanhf(cn.w);

    reinterpret_cast<float4*>(out)[idx]                 = hn;  // h_new
    reinterpret_cast<float4*>(out)[idx + 4096 * 256]    = cn;  // c_new
}

extern "C" void kernel_launch(void* const* d_in, const int* in_sizes, int n_in,
                              void* d_out, int out_size)
{
    (void)in_sizes; (void)n_in; (void)out_size;
    const float* x  = (const float*)d_in[0];   // input  [4096,1024]
    const float* ht = (const float*)d_in[1];   // h_t    [4096,1024]
    const float* ct = (const float*)d_in[2];   // c_t    [4096,1024]
    const float* wi = (const float*)d_in[3];   // w_i    [1024,4096]
    const float* wh = (const float*)d_in[4];   // w_h    [1024,4096]
    const float* bi = (const float*)d_in[5];   // b_i    [4096]
    const float* bh = (const float*)d_in[6];   // b_h    [4096]
    float* out = (float*)d_out;                // [h_new | c_new], 2*4096*1024 fp32

    dim3 grid(4096 / BN, 4096 / BM);
    lstm_gemm_kernel<<<grid, 256>>>(x, ht, wi, wh, bi, bh);
    lstm_act_kernel<<<4096, 256>>>(ct, out);
}

// round 3
// speedup vs baseline: 2.4099x; 2.4099x over previous
#include <cuda_runtime.h>
#include <cuda_bf16.h>
#include <cstdint>
#include <math.h>

// LSTM cell B=4096, I=H=1024.
// GEMM ifgo[4096,4096] = [x|h] @ [wi;wh] + bias via mma.sync bf16 hi/lo split
// (3 MMAs: hi*hi + hi*lo + lo*hi, fp32 accum -> ~1e-5 rel err).
// NOTE: build targets plain sm_103 (no 'a' features) -> tcgen05 unavailable;
// mma.sync/ldmatrix/cp.async are the legal tensor path.

#define BM 128
#define BN 128
#define BK 32
#define KTOT 2048
#define NITER (KTOT / BK)

// smem: padded rows, 32+8 halves = 80B pitch (conflict-free for ldmatrix)
#define ROWB 80
#define TILE_B (128 * ROWB)            // 10240 B per tile
#define OFF_AHI 0
#define OFF_ALO (TILE_B)
#define OFF_BHI (2 * TILE_B)
#define OFF_BLO (3 * TILE_B)
#define STAGE   (4 * TILE_B)           // 40960 B
#define SMEM_TOTAL (2 * STAGE)         // 81920 B

// ---- scratch (allocation-free rule: __device__ globals) ----
__device__ float g_ifgo[4096ull * 4096ull];                              // 64 MB
__device__ __nv_bfloat16 g_Ahi[4096ull * 2048], g_Alo[4096ull * 2048];   // 16+16 MB
__device__ __nv_bfloat16 g_Whi[4096ull * 2048], g_Wlo[4096ull * 2048];   // 16+16 MB (N-major: [n][k])

__device__ __forceinline__ uint32_t smem_u32(const void* p) {
    uint32_t a;
    asm("{ .reg .u64 t; cvta.to.shared.u64 t, %1; cvt.u32.u64 %0, t; }" : "=r"(a) : "l"(p));
    return a;
}
__device__ __forceinline__ void cp_async16(uint32_t s, const void* g) {
    asm volatile("cp.async.cg.shared.global [%0], [%1], 16;\n" :: "r"(s), "l"(g));
}
#define CP_COMMIT() asm volatile("cp.async.commit_group;\n" ::: "memory")
#define CP_WAIT(n)  asm volatile("cp.async.wait_group %0;\n" :: "n"(n) : "memory")

__device__ __forceinline__ void ldsm_x4(uint32_t* r, uint32_t addr) {
    asm volatile("ldmatrix.sync.aligned.m8n8.x4.shared.b16 {%0,%1,%2,%3}, [%4];"
                 : "=r"(r[0]), "=r"(r[1]), "=r"(r[2]), "=r"(r[3]) : "r"(addr));
}
__device__ __forceinline__ void mma_bf16(float* c, const uint32_t* a, const uint32_t* b) {
    asm volatile("mma.sync.aligned.m16n8k16.row.col.f32.bf16.bf16.f32 "
                 "{%0,%1,%2,%3}, {%4,%5,%6,%7}, {%8,%9}, {%0,%1,%2,%3};"
                 : "+f"(c[0]), "+f"(c[1]), "+f"(c[2]), "+f"(c[3])
                 : "r"(a[0]), "r"(a[1]), "r"(a[2]), "r"(a[3]), "r"(b[0]), "r"(b[1]));
}

// ============================================================
// pre-kernel 1: A = [x|h] -> bf16 hi/lo, row-major [4096, 2048]
// ============================================================
__global__ __launch_bounds__(256)
void convert_a(const float* __restrict__ x, const float* __restrict__ h)
{
    const int idx = blockIdx.x * 256 + threadIdx.x;   // over 4096*512 float4
    const int m = idx >> 9;
    const int kq = idx & 511;
    float4 v = (kq < 256)
        ? reinterpret_cast<const float4*>(x)[(size_t)m * 256 + kq]
        : reinterpret_cast<const float4*>(h)[(size_t)m * 256 + (kq - 256)];
    __nv_bfloat16 h0 = __float2bfloat16(v.x), h1 = __float2bfloat16(v.y);
    __nv_bfloat16 h2 = __float2bfloat16(v.z), h3 = __float2bfloat16(v.w);
    __nv_bfloat16 l0 = __float2bfloat16(v.x - __bfloat162float(h0));
    __nv_bfloat16 l1 = __float2bfloat16(v.y - __bfloat162float(h1));
    __nv_bfloat16 l2 = __float2bfloat16(v.z - __bfloat162float(h2));
    __nv_bfloat16 l3 = __float2bfloat16(v.w - __bfloat162float(h3));
    __nv_bfloat162 hp0(h0, h1), hp1(h2, h3), lp0(l0, l1), lp1(l2, l3);
    uint2 hv, lv;
    hv.x = *reinterpret_cast<uint32_t*>(&hp0); hv.y = *reinterpret_cast<uint32_t*>(&hp1);
    lv.x = *reinterpret_cast<uint32_t*>(&lp0); lv.y = *reinterpret_cast<uint32_t*>(&lp1);
    reinterpret_cast<uint2*>(g_Ahi)[idx] = hv;
    reinterpret_cast<uint2*>(g_Alo)[idx] = lv;
}

// ============================================================
// pre-kernel 2: Wt[n][k] = (k<1024 ? wi[k][n] : wh[k-1024][n]) -> bf16 hi/lo
// ============================================================
__global__ __launch_bounds__(256)
void convert_w(const float* __restrict__ wi, const float* __restrict__ wh)
{
    __shared__ float tile[32][33];
    const int k0 = blockIdx.x * 32;
    const int n0 = blockIdx.y * 32;
    const int tx = threadIdx.x, ty = threadIdx.y;   // (32, 8)
    #pragma unroll
    for (int j = 0; j < 4; j++) {
        int k = k0 + ty + j * 8;
        const float* w = (k < 1024) ? (wi + (size_t)k * 4096) : (wh + (size_t)(k - 1024) * 4096);
        tile[ty + j * 8][tx] = w[n0 + tx];
    }
    __syncthreads();
    #pragma unroll
    for (int j = 0; j < 4; j++) {
        int n = n0 + ty + j * 8;
        float v = tile[tx][ty + j * 8];
        __nv_bfloat16 hi = __float2bfloat16(v);
        __nv_bfloat16 lo = __float2bfloat16(v - __bfloat162float(hi));
        g_Whi[(size_t)n * 2048 + k0 + tx] = hi;
        g_Wlo[(size_t)n * 2048 + k0 + tx] = lo;
    }
}

// ============================================================
// GEMM: mma.sync bf16 hi/lo, 128x128x32 CTA tile, 8 warps (4m x 2n), warp 32x64
// ============================================================
__global__ __launch_bounds__(256)
void lstm_gemm_mma()
{
    extern __shared__ char smem[];
    const uint32_t sb = smem_u32(smem);
    const int tid = threadIdx.x;
    const int lane = tid & 31;
    const int w = tid >> 5;
    const int wm0 = (w & 3) * 32;       // warp m offset in tile
    const int wn0 = (w >> 2) * 64;      // warp n offset in tile
    const int bm = blockIdx.y * BM;
    const int bn = blockIdx.x * BN;

    float acc[2][8][4];
    #pragma unroll
    for (int i = 0; i < 2; i++)
        #pragma unroll
        for (int j = 0; j < 8; j++)
            #pragma unroll
            for (int q = 0; q < 4; q++) acc[i][j][q] = 0.f;

    // loader: each tile 128 rows x 64B data in 80B-pitch rows -> 512 cp16, 2/thread
    const int lrow0 = tid >> 1;          // rows tid/2 and tid/2+... (2 chunks per thread per tile)
    auto load_stage = [&](int c, int buf) {
        const int kk = c * BK;
        const uint32_t st = sb + buf * STAGE;
        #pragma unroll
        for (int t = 0; t < 2; t++) {
            int idx = tid + t * 256;     // 0..511
            int row = idx >> 2;          // 0..127
            int c16 = idx & 3;           // 16B chunk in row
            uint32_t so = (uint32_t)(row * ROWB + c16 * 16);
            size_t ga = (size_t)(bm + row) * KTOT + kk + c16 * 8;
            size_t gb = (size_t)(bn + row) * KTOT + kk + c16 * 8;
            cp_async16(st + OFF_AHI + so, g_Ahi + ga);
            cp_async16(st + OFF_ALO + so, g_Alo + ga);
            cp_async16(st + OFF_BHI + so, g_Whi + gb);
            cp_async16(st + OFF_BLO + so, g_Wlo + gb);
        }
        CP_COMMIT();
    };
    (void)lrow0;

    load_stage(0, 0);

    for (int c = 0; c < NITER; c++) {
        const int buf = c & 1;
        if (c + 1 < NITER) {
            load_stage(c + 1, 1 - buf);
            CP_WAIT(1);
        } else {
            CP_WAIT(0);
        }
        __syncthreads();

        const uint32_t st = sb + buf * STAGE;
        #pragma unroll
        for (int ks = 0; ks < 2; ks++) {
            // A fragments (2 m-tiles, hi+lo)
            uint32_t ah[2][4], al[2][4];
            #pragma unroll
            for (int tm = 0; tm < 2; tm++) {
                uint32_t ra = (uint32_t)((wm0 + tm * 16 + (lane & 15)) * ROWB
                                         + ks * 32 + ((lane >> 4) << 4));
                ldsm_x4(ah[tm], st + OFF_AHI + ra);
                ldsm_x4(al[tm], st + OFF_ALO + ra);
            }
            // B fragments: 4 ldmatrix.x4 cover 8 n-tiles (hi), same for lo
            #pragma unroll
            for (int tn4 = 0; tn4 < 4; tn4++) {
                uint32_t rb = (uint32_t)((wn0 + tn4 * 16 + ((lane >> 4) << 3) + (lane & 7)) * ROWB
                                         + ks * 32 + (((lane >> 3) & 1) << 4));
                uint32_t bh[4], bl[4];
                ldsm_x4(bh, st + OFF_BHI + rb);
                ldsm_x4(bl, st + OFF_BLO + rb);
                #pragma unroll
                for (int tm = 0; tm < 2; tm++) {
                    #pragma unroll
                    for (int s = 0; s < 2; s++) {
                        float* cc = acc[tm][tn4 * 2 + s];
                        mma_bf16(cc, ah[tm], &bh[2 * s]);   // hi*hi
                        mma_bf16(cc, ah[tm], &bl[2 * s]);   // hi*lo
                        mma_bf16(cc, al[tm], &bh[2 * s]);   // lo*hi
                    }
                }
            }
        }
        __syncthreads();
    }

    // epilogue -> g_ifgo
    const int quad = lane >> 2;
    const int tq = lane & 3;
    #pragma unroll
    for (int tm = 0; tm < 2; tm++) {
        const int m0 = bm + wm0 + tm * 16 + quad;
        #pragma unroll
        for (int tn = 0; tn < 8; tn++) {
            const int n = bn + wn0 + tn * 8 + 2 * tq;
            float2 v0 = make_float2(acc[tm][tn][0], acc[tm][tn][1]);
            float2 v1 = make_float2(acc[tm][tn][2], acc[tm][tn][3]);
            *reinterpret_cast<float2*>(&g_ifgo[(size_t)m0 * 4096 + n]) = v0;
            *reinterpret_cast<float2*>(&g_ifgo[(size_t)(m0 + 8) * 4096 + n]) = v1;
        }
    }
}

// ============================================================
// activation: gates + bias -> h_new, c_new
// ============================================================
__device__ __forceinline__ float sigmoidf_fast(float v) {
    return 1.f / (1.f + __expf(-v));
}

__global__ __launch_bounds__(256)
void lstm_act(const float* __restrict__ c_t,
              const float* __restrict__ bi, const float* __restrict__ bh,
              float* __restrict__ out)
{
    const int idx = blockIdx.x * blockDim.x + threadIdx.x;
    const int b = idx >> 8;
    const int hq = idx & 255;

    const float4* row = reinterpret_cast<const float4*>(g_ifgo + (size_t)b * 4096);
    const float4* bi4 = reinterpret_cast<const float4*>(bi);
    const float4* bh4 = reinterpret_cast<const float4*>(bh);

    float4 vi = row[hq],       vf = row[hq + 256];
    float4 vg = row[hq + 512], vo = row[hq + 768];
    float4 vc = reinterpret_cast<const float4*>(c_t)[idx];

    float4 ci = bi4[hq],       cf = bi4[hq + 256];
    float4 cg = bi4[hq + 512], co = bi4[hq + 768];
    float4 di = bh4[hq],       df = bh4[hq + 256];
    float4 dg = bh4[hq + 512], dh = bh4[hq + 768];
    vi.x += ci.x + di.x; vi.y += ci.y + di.y; vi.z += ci.z + di.z; vi.w += ci.w + di.w;
    vf.x += cf.x + df.x; vf.y += cf.y + df.y; vf.z += cf.z + df.z; vf.w += cf.w + df.w;
    vg.x += cg.x + dg.x; vg.y += cg.y + dg.y; vg.z += cg.z + dg.z; vg.w += cg.w + dg.w;
    vo.x += co.x + dh.x; vo.y += co.y + dh.y; vo.z += co.z + dh.z; vo.w += co.w + dh.w;

    float4 cn, hn;
    cn.x = sigmoidf_fast(vf.x) * vc.x + sigmoidf_fast(vi.x) * tanhf(vg.x);
    cn.y = sigmoidf_fast(vf.y) * vc.y + sigmoidf_fast(vi.y) * tanhf(vg.y);
    cn.z = sigmoidf_fast(vf.z) * vc.z + sigmoidf_fast(vi.z) * tanhf(vg.z);
    cn.w = sigmoidf_fast(vf.w) * vc.w + sigmoidf_fast(vi.w) * tanhf(vg.w);
    hn.x = sigmoidf_fast(vo.x) * tanhf(cn.x);
    hn.y = sigmoidf_fast(vo.y) * tanhf(cn.y);
    hn.z = sigmoidf_fast(vo.z) * tanhf(cn.z);
    hn.w = sigmoidf_fast(vo.w) * tanhf(cn.w);

    reinterpret_cast<float4*>(out)[idx]              = hn;  // h_new
    reinterpret_cast<float4*>(out)[idx + 4096 * 256] = cn;  // c_new
}

// ============================================================
extern "C" void kernel_launch(void* const* d_in, const int* in_sizes, int n_in,
                              void* d_out, int out_size)
{
    (void)in_sizes; (void)n_in; (void)out_size;
    const float* x  = (const float*)d_in[0];
    const float* ht = (const float*)d_in[1];
    const float* ct = (const float*)d_in[2];
    const float* wi = (const float*)d_in[3];
    const float* wh = (const float*)d_in[4];
    const float* bi = (const float*)d_in[5];
    const float* bh = (const float*)d_in[6];
    float* out = (float*)d_out;

    cudaFuncSetAttribute(lstm_gemm_mma, cudaFuncAttributeMaxDynamicSharedMemorySize, SMEM_TOTAL);

    convert_a<<<4096 * 512 / 256, 256>>>(x, ht);
    convert_w<<<dim3(2048 / 32, 4096 / 32), dim3(32, 8)>>>(wi, wh);
    lstm_gemm_mma<<<dim3(4096 / BN, 4096 / BM), 256, SMEM_TOTAL>>>();
    lstm_act<<<4096, 256>>>(ct, bi, bh, out);
}